// round 4
// baseline (speedup 1.0000x reference)
#include <cuda_runtime.h>
#include <cuda_bf16.h>

#define NN 20000
#define NPAD 20032
#define NE 320000
#define F0 10
#define F1 256
#define F2 128

// ---------------- scratch (device globals; no allocation allowed) ----------
__device__ int   g_cnt[NN];
__device__ int   g_rowptr[NN + 1];
__device__ int   g_woff[NN];
__device__ int   g_csr[NE];          // src index per CSR slot (grouped by dst)
__device__ float g_dinv[NN];
__device__ float g_aggx[NN * F0];    // A_norm @ x
__device__ float g_h1[NPAD * F1];    // relu(aggx @ W1 + b1)  (row-padded)
__device__ float g_t2[NPAD * F2];    // h1 @ W2               (row-padded)
__device__ float g_t3[NN];           // relu(A@t2+b2) @ W3

// ---------------- CSR build ------------------------------------------------
__global__ void k_zero_cnt() {
    int i = blockIdx.x * blockDim.x + threadIdx.x;
    if (i < NN) g_cnt[i] = 0;
}

__global__ void k_hist(const int* __restrict__ dst) {
    int e = blockIdx.x * blockDim.x + threadIdx.x;
    if (e < NE) atomicAdd(&g_cnt[dst[e]], 1);
}

// Single-block scan, ONE sync round: each thread owns 20 contiguous counts,
// scans them in registers, warp-shuffle scan over the 1024 thread totals.
// Also computes g_dinv (fused; it only needs g_cnt).
__global__ void k_scan_fused() {
    __shared__ int wsum[32];
    const int PER = 20;                       // 1024*20 = 20480 >= NN
    int tid  = threadIdx.x;
    int lane = tid & 31, w = tid >> 5;
    int base = tid * PER;

    int pref[PER];
    int s = 0;
    #pragma unroll
    for (int j = 0; j < PER; j++) {
        int idx = base + j;
        int c = (idx < NN) ? g_cnt[idx] : 0;
        pref[j] = s;                          // exclusive within thread
        s += c;
        if (idx < NN) g_dinv[idx] = rsqrtf((float)(c + 1));
    }

    // warp inclusive scan of thread totals
    int incl = s;
    #pragma unroll
    for (int o = 1; o < 32; o <<= 1) {
        int t = __shfl_up_sync(0xffffffffu, incl, o);
        if (lane >= o) incl += t;
    }
    if (lane == 31) wsum[w] = incl;
    __syncthreads();
    if (w == 0) {
        int t = wsum[lane];
        int ss = t;
        #pragma unroll
        for (int o = 1; o < 32; o <<= 1) {
            int u = __shfl_up_sync(0xffffffffu, ss, o);
            if (lane >= o) ss += u;
        }
        wsum[lane] = ss - t;                  // exclusive warp offsets
    }
    __syncthreads();

    int thread_excl = wsum[w] + incl - s;
    #pragma unroll
    for (int j = 0; j < PER; j++) {
        int idx = base + j;
        if (idx < NN) {
            int e = thread_excl + pref[j];
            g_rowptr[idx] = e;
            g_woff[idx]   = e;
        }
    }
    if (tid == 1023) g_rowptr[NN] = thread_excl + s;  // == NE
}

__global__ void k_scatter(const int* __restrict__ src, const int* __restrict__ dst) {
    int e = blockIdx.x * blockDim.x + threadIdx.x;
    if (e < NE) {
        int pos = atomicAdd(&g_woff[dst[e]], 1);
        g_csr[pos] = src[e];
    }
}

// ---------------- layer 1: aggregate x (F=10), then GEMM -------------------
__global__ void k_aggx(const float* __restrict__ x) {
    int w = (blockIdx.x * blockDim.x + threadIdx.x) >> 5;
    int lane = threadIdx.x & 31;
    if (w >= NN) return;
    float dn = g_dinv[w];
    float acc = 0.f;
    if (lane < F0) acc = dn * x[w * F0 + lane];
    int b = g_rowptr[w], e = g_rowptr[w + 1];
    for (int i = b; i < e; i++) {
        int s = g_csr[i];
        float c = g_dinv[s];
        if (lane < F0) acc += c * x[s * F0 + lane];
    }
    if (lane < F0) g_aggx[w * F0 + lane] = dn * acc;
}

// [NN,10] @ [10,256] + b1, relu.  20 rows per block, 256 threads = 1 col each.
__global__ void k_gemm1(const float* __restrict__ W1, const float* __restrict__ b1) {
    __shared__ float Ws[F0 * F1];   // 10 KB
    __shared__ float bs[F1];
    __shared__ float ax[20 * F0];
    int t = threadIdx.x;
    for (int i = t; i < F0 * F1; i += 256) Ws[i] = W1[i];
    bs[t] = b1[t];
    int r0 = blockIdx.x * 20;
    for (int i = t; i < 20 * F0; i += 256) ax[i] = g_aggx[r0 * F0 + i];
    __syncthreads();
    #pragma unroll 4
    for (int r = 0; r < 20; r++) {
        float acc = bs[t];
        #pragma unroll
        for (int k = 0; k < F0; k++) acc += ax[r * F0 + k] * Ws[k * F1 + t];
        g_h1[(r0 + r) * F1 + t] = fmaxf(acc, 0.f);
    }
}

// ---------------- layer 2 GEMM: [NN,256] @ [256,128] -> g_t2 ---------------
// Tile: 64 rows x 128 cols, k-tile 32, 256 threads, 8x4 register tile.
// A staged TRANSPOSED in smem (hsT[k][row], row padded to 68 floats = 272B,
// 16B-aligned rows and conflict-free) so per-kk A fragments are LDS.128.
__global__ void k_gemm2(const float* __restrict__ W2) {
    __shared__ float hsT[32][68];
    __shared__ float ws[32][128];
    int t  = threadIdx.x;
    int tx = t & 31;         // cols tx*4 .. tx*4+3
    int ty = t >> 5;         // rows ty*8 .. ty*8+7
    int r0 = blockIdx.x * 64;
    float acc[8][4] = {};

    int lrow = t & 63;       // 0..63 (A-load row)
    int lkg  = t >> 6;       // 0..3  (A-load k group of 8)

    for (int k0 = 0; k0 < F1; k0 += 32) {
        #pragma unroll
        for (int h = 0; h < 2; h++) {
            int kk = lkg * 8 + h * 4;
            float4 v = *(const float4*)&g_h1[(r0 + lrow) * F1 + k0 + kk];
            hsT[kk + 0][lrow] = v.x;
            hsT[kk + 1][lrow] = v.y;
            hsT[kk + 2][lrow] = v.z;
            hsT[kk + 3][lrow] = v.w;
        }
        #pragma unroll
        for (int p = 0; p < 4; p++) {
            int kk = ty + p * 8;
            *(float4*)&ws[kk][tx * 4] = *(const float4*)&W2[(k0 + kk) * F2 + tx * 4];
        }
        __syncthreads();
        #pragma unroll
        for (int kk = 0; kk < 32; kk++) {
            float4 bv = *(const float4*)&ws[kk][tx * 4];
            float4 a0 = *(const float4*)&hsT[kk][ty * 8];
            float4 a1 = *(const float4*)&hsT[kk][ty * 8 + 4];
            acc[0][0] += a0.x * bv.x; acc[0][1] += a0.x * bv.y; acc[0][2] += a0.x * bv.z; acc[0][3] += a0.x * bv.w;
            acc[1][0] += a0.y * bv.x; acc[1][1] += a0.y * bv.y; acc[1][2] += a0.y * bv.z; acc[1][3] += a0.y * bv.w;
            acc[2][0] += a0.z * bv.x; acc[2][1] += a0.z * bv.y; acc[2][2] += a0.z * bv.z; acc[2][3] += a0.z * bv.w;
            acc[3][0] += a0.w * bv.x; acc[3][1] += a0.w * bv.y; acc[3][2] += a0.w * bv.z; acc[3][3] += a0.w * bv.w;
            acc[4][0] += a1.x * bv.x; acc[4][1] += a1.x * bv.y; acc[4][2] += a1.x * bv.z; acc[4][3] += a1.x * bv.w;
            acc[5][0] += a1.y * bv.x; acc[5][1] += a1.y * bv.y; acc[5][2] += a1.y * bv.z; acc[5][3] += a1.y * bv.w;
            acc[6][0] += a1.z * bv.x; acc[6][1] += a1.z * bv.y; acc[6][2] += a1.z * bv.z; acc[6][3] += a1.z * bv.w;
            acc[7][0] += a1.w * bv.x; acc[7][1] += a1.w * bv.y; acc[7][2] += a1.w * bv.z; acc[7][3] += a1.w * bv.w;
        }
        __syncthreads();
    }
    #pragma unroll
    for (int i = 0; i < 8; i++) {
        *(float4*)&g_t2[(r0 + ty * 8 + i) * F2 + tx * 4] =
            make_float4(acc[i][0], acc[i][1], acc[i][2], acc[i][3]);
    }
}

// ------- layer 2 aggregation + bias + relu + layer-3 dot (fused) -----------
// One warp per node. h2 row lives only in registers; dot with W3 + warp
// reduction writes the scalar g_t3 directly (g_h2 array eliminated).
__global__ void k_agg2dot(const float* __restrict__ b2, const float* __restrict__ W3) {
    int w = (blockIdx.x * blockDim.x + threadIdx.x) >> 5;
    int lane = threadIdx.x & 31;
    if (w >= NN) return;
    float dn = g_dinv[w];
    int c4 = lane * 4;
    float4 sv = *(const float4*)&g_t2[w * F2 + c4];
    float4 acc = make_float4(dn * sv.x, dn * sv.y, dn * sv.z, dn * sv.w);
    int b = g_rowptr[w], e = g_rowptr[w + 1];
    for (int i = b; i < e; i++) {
        int s = g_csr[i];
        float c = g_dinv[s];
        float4 v = *(const float4*)&g_t2[s * F2 + c4];
        acc.x += c * v.x; acc.y += c * v.y; acc.z += c * v.z; acc.w += c * v.w;
    }
    float4 bb = *(const float4*)&b2[c4];
    float4 h;
    h.x = fmaxf(dn * acc.x + bb.x, 0.f);
    h.y = fmaxf(dn * acc.y + bb.y, 0.f);
    h.z = fmaxf(dn * acc.z + bb.z, 0.f);
    h.w = fmaxf(dn * acc.w + bb.w, 0.f);
    float4 v3 = *(const float4*)&W3[c4];
    float s = h.x * v3.x + h.y * v3.y + h.z * v3.z + h.w * v3.w;
    #pragma unroll
    for (int o = 16; o > 0; o >>= 1) s += __shfl_down_sync(0xffffffffu, s, o);
    if (lane == 0) g_t3[w] = s;
}

// ---------------- final aggregation over t3 --------------------------------
__global__ void k_agg3(const float* __restrict__ b3, float* __restrict__ out) {
    int n = blockIdx.x * blockDim.x + threadIdx.x;
    if (n >= NN) return;
    float dn = g_dinv[n];
    float acc = dn * g_t3[n];
    int b = g_rowptr[n], e = g_rowptr[n + 1];
    for (int i = b; i < e; i++) {
        int s = g_csr[i];
        acc += g_dinv[s] * g_t3[s];
    }
    out[n] = dn * acc + b3[0];
}

// ---------------- launch ----------------------------------------------------
extern "C" void kernel_launch(void* const* d_in, const int* in_sizes, int n_in,
                              void* d_out, int out_size) {
    const float* x   = (const float*)d_in[0];
    const int*   ei  = (const int*)d_in[1];
    const float* W1  = (const float*)d_in[2];
    const float* b1  = (const float*)d_in[3];
    const float* W2  = (const float*)d_in[4];
    const float* b2  = (const float*)d_in[5];
    const float* W3  = (const float*)d_in[6];
    const float* b3  = (const float*)d_in[7];
    float* out = (float*)d_out;
    const int* src = ei;
    const int* dst = ei + NE;

    k_zero_cnt<<<(NN + 255) / 256, 256>>>();
    k_hist<<<(NE + 255) / 256, 256>>>(dst);
    k_scan_fused<<<1, 1024>>>();
    k_scatter<<<(NE + 255) / 256, 256>>>(src, dst);

    k_aggx<<<(NN * 32 + 255) / 256, 256>>>(x);
    k_gemm1<<<NN / 20, 256>>>(W1, b1);
    k_gemm2<<<(NN + 63) / 64, 256>>>(W2);
    k_agg2dot<<<(NN * 32 + 255) / 256, 256>>>(b2, W3);
    k_agg3<<<(NN + 255) / 256, 256>>>(b3, out);
}

// round 5
// speedup vs baseline: 1.0178x; 1.0178x over previous
#include <cuda_runtime.h>
#include <cuda_bf16.h>

#define NN 20000
#define NE 320000
#define F0 10
#define F1 256
#define F2 128

// ---------------- scratch (device globals; no allocation allowed) ----------
__device__ int   g_cnt[NN];
__device__ int   g_rowptr[NN + 1];
__device__ int   g_woff[NN];
__device__ int   g_csr[NE];          // src index per CSR slot (grouped by dst)
__device__ float g_dinv[NN];
__device__ float g_aggx[NN * F0];    // A_norm @ x
__device__ float g_h1[NN * F1];      // relu(aggx @ W1 + b1)
__device__ float g_t2[NN * F2];      // h1 @ W2
__device__ float g_t3[NN];           // relu(A@t2+b2) @ W3

// ---------------- CSR build ------------------------------------------------
__global__ void k_zero_cnt() {
    int i = blockIdx.x * blockDim.x + threadIdx.x;
    if (i < NN) g_cnt[i] = 0;
}

// 4 edges per thread, blocked-cyclic: coalesced loads, 4 independent atomics.
__global__ void k_hist(const int* __restrict__ dst) {
    int base = blockIdx.x * (blockDim.x * 4) + threadIdx.x;
    #pragma unroll
    for (int j = 0; j < 4; j++) {
        int e = base + j * blockDim.x;
        if (e < NE) atomicAdd(&g_cnt[dst[e]], 1);
    }
}

// Single-block scan, one sync round; fuses g_dinv.
__global__ void k_scan_fused() {
    __shared__ int wsum[32];
    const int PER = 20;                       // 1024*20 = 20480 >= NN
    int tid  = threadIdx.x;
    int lane = tid & 31, w = tid >> 5;
    int base = tid * PER;

    int pref[PER];
    int s = 0;
    #pragma unroll
    for (int j = 0; j < PER; j++) {
        int idx = base + j;
        int c = (idx < NN) ? g_cnt[idx] : 0;
        pref[j] = s;
        s += c;
        if (idx < NN) g_dinv[idx] = rsqrtf((float)(c + 1));
    }

    int incl = s;
    #pragma unroll
    for (int o = 1; o < 32; o <<= 1) {
        int t = __shfl_up_sync(0xffffffffu, incl, o);
        if (lane >= o) incl += t;
    }
    if (lane == 31) wsum[w] = incl;
    __syncthreads();
    if (w == 0) {
        int t = wsum[lane];
        int ss = t;
        #pragma unroll
        for (int o = 1; o < 32; o <<= 1) {
            int u = __shfl_up_sync(0xffffffffu, ss, o);
            if (lane >= o) ss += u;
        }
        wsum[lane] = ss - t;
    }
    __syncthreads();

    int thread_excl = wsum[w] + incl - s;
    #pragma unroll
    for (int j = 0; j < PER; j++) {
        int idx = base + j;
        if (idx < NN) {
            int e = thread_excl + pref[j];
            g_rowptr[idx] = e;
            g_woff[idx]   = e;
        }
    }
    if (tid == 1023) g_rowptr[NN] = thread_excl + s;  // == NE
}

// 4 edges per thread: 4 independent atomic->STG chains in flight.
__global__ void k_scatter(const int* __restrict__ src, const int* __restrict__ dst) {
    int base = blockIdx.x * (blockDim.x * 4) + threadIdx.x;
    int e0 = base;
    int e1 = base + blockDim.x;
    int e2 = base + blockDim.x * 2;
    int e3 = base + blockDim.x * 3;
    int d0 = (e0 < NE) ? dst[e0] : 0;
    int d1 = (e1 < NE) ? dst[e1] : 0;
    int d2 = (e2 < NE) ? dst[e2] : 0;
    int d3 = (e3 < NE) ? dst[e3] : 0;
    int p0 = (e0 < NE) ? atomicAdd(&g_woff[d0], 1) : 0;
    int p1 = (e1 < NE) ? atomicAdd(&g_woff[d1], 1) : 0;
    int p2 = (e2 < NE) ? atomicAdd(&g_woff[d2], 1) : 0;
    int p3 = (e3 < NE) ? atomicAdd(&g_woff[d3], 1) : 0;
    if (e0 < NE) g_csr[p0] = src[e0];
    if (e1 < NE) g_csr[p1] = src[e1];
    if (e2 < NE) g_csr[p2] = src[e2];
    if (e3 < NE) g_csr[p3] = src[e3];
}

// ---------------- layer 1: aggregate x (F=10), then GEMM -------------------
__global__ void k_aggx(const float* __restrict__ x) {
    int w = (blockIdx.x * blockDim.x + threadIdx.x) >> 5;
    int lane = threadIdx.x & 31;
    if (w >= NN) return;
    float dn = g_dinv[w];
    float acc = 0.f;
    if (lane < F0) acc = dn * x[w * F0 + lane];
    int b = g_rowptr[w], e = g_rowptr[w + 1];
    for (int i = b; i < e; i++) {
        int s = g_csr[i];
        float c = g_dinv[s];
        if (lane < F0) acc += c * x[s * F0 + lane];
    }
    if (lane < F0) g_aggx[w * F0 + lane] = dn * acc;
}

// [NN,10] @ [10,256] + b1, relu.  20 rows per block, 256 threads = 1 col each.
__global__ void k_gemm1(const float* __restrict__ W1, const float* __restrict__ b1) {
    __shared__ float Ws[F0 * F1];   // 10 KB
    __shared__ float bs[F1];
    __shared__ float ax[20 * F0];
    int t = threadIdx.x;
    for (int i = t; i < F0 * F1; i += 256) Ws[i] = W1[i];
    bs[t] = b1[t];
    int r0 = blockIdx.x * 20;
    for (int i = t; i < 20 * F0; i += 256) ax[i] = g_aggx[r0 * F0 + i];
    __syncthreads();
    #pragma unroll 4
    for (int r = 0; r < 20; r++) {
        float acc = bs[t];
        #pragma unroll
        for (int k = 0; k < F0; k++) acc += ax[r * F0 + k] * Ws[k * F1 + t];
        g_h1[(r0 + r) * F1 + t] = fmaxf(acc, 0.f);
    }
}

// ---------------- layer 2 GEMM: [NN,256] @ [256,128] -> g_t2 ---------------
// Proven 32x128 tile, k-tile 32, 256 threads, 4x4 register tile (R0 version).
__global__ void k_gemm2(const float* __restrict__ W2) {
    __shared__ float hs[32][33];
    __shared__ float ws[32][128];
    int t  = threadIdx.x;
    int tx = t & 31;
    int ty = t >> 5;
    int r0 = blockIdx.x * 32;
    float acc[4][4];
    #pragma unroll
    for (int i = 0; i < 4; i++)
        #pragma unroll
        for (int j = 0; j < 4; j++) acc[i][j] = 0.f;

    int li = t >> 3;
    int lk = (t & 7) * 4;
    for (int k0 = 0; k0 < F1; k0 += 32) {
        float4 hv = *(const float4*)&g_h1[(r0 + li) * F1 + k0 + lk];
        hs[li][lk + 0] = hv.x; hs[li][lk + 1] = hv.y;
        hs[li][lk + 2] = hv.z; hs[li][lk + 3] = hv.w;
        #pragma unroll
        for (int p = 0; p < 4; p++) {
            int kk = ty + p * 8;
            *(float4*)&ws[kk][tx * 4] = *(const float4*)&W2[(k0 + kk) * F2 + tx * 4];
        }
        __syncthreads();
        #pragma unroll
        for (int kk = 0; kk < 32; kk++) {
            float4 bv = *(const float4*)&ws[kk][tx * 4];
            float a0 = hs[ty * 4 + 0][kk];
            float a1 = hs[ty * 4 + 1][kk];
            float a2 = hs[ty * 4 + 2][kk];
            float a3 = hs[ty * 4 + 3][kk];
            acc[0][0] += a0 * bv.x; acc[0][1] += a0 * bv.y; acc[0][2] += a0 * bv.z; acc[0][3] += a0 * bv.w;
            acc[1][0] += a1 * bv.x; acc[1][1] += a1 * bv.y; acc[1][2] += a1 * bv.z; acc[1][3] += a1 * bv.w;
            acc[2][0] += a2 * bv.x; acc[2][1] += a2 * bv.y; acc[2][2] += a2 * bv.z; acc[2][3] += a2 * bv.w;
            acc[3][0] += a3 * bv.x; acc[3][1] += a3 * bv.y; acc[3][2] += a3 * bv.z; acc[3][3] += a3 * bv.w;
        }
        __syncthreads();
    }
    #pragma unroll
    for (int i = 0; i < 4; i++) {
        float4 o = make_float4(acc[i][0], acc[i][1], acc[i][2], acc[i][3]);
        *(float4*)&g_t2[(r0 + ty * 4 + i) * F2 + tx * 4] = o;
    }
}

// ------- layer 2 aggregation + bias + relu + layer-3 dot (fused) -----------
__global__ void k_agg2dot(const float* __restrict__ b2, const float* __restrict__ W3) {
    int w = (blockIdx.x * blockDim.x + threadIdx.x) >> 5;
    int lane = threadIdx.x & 31;
    if (w >= NN) return;
    float dn = g_dinv[w];
    int c4 = lane * 4;
    float4 sv = *(const float4*)&g_t2[w * F2 + c4];
    float4 acc = make_float4(dn * sv.x, dn * sv.y, dn * sv.z, dn * sv.w);
    int b = g_rowptr[w], e = g_rowptr[w + 1];
    for (int i = b; i < e; i++) {
        int s = g_csr[i];
        float c = g_dinv[s];
        float4 v = *(const float4*)&g_t2[s * F2 + c4];
        acc.x += c * v.x; acc.y += c * v.y; acc.z += c * v.z; acc.w += c * v.w;
    }
    float4 bb = *(const float4*)&b2[c4];
    float4 h;
    h.x = fmaxf(dn * acc.x + bb.x, 0.f);
    h.y = fmaxf(dn * acc.y + bb.y, 0.f);
    h.z = fmaxf(dn * acc.z + bb.z, 0.f);
    h.w = fmaxf(dn * acc.w + bb.w, 0.f);
    float4 v3 = *(const float4*)&W3[c4];
    float s = h.x * v3.x + h.y * v3.y + h.z * v3.z + h.w * v3.w;
    #pragma unroll
    for (int o = 16; o > 0; o >>= 1) s += __shfl_down_sync(0xffffffffu, s, o);
    if (lane == 0) g_t3[w] = s;
}

// ---------------- final aggregation over t3 --------------------------------
__global__ void k_agg3(const float* __restrict__ b3, float* __restrict__ out) {
    int n = blockIdx.x * blockDim.x + threadIdx.x;
    if (n >= NN) return;
    float dn = g_dinv[n];
    float acc = dn * g_t3[n];
    int b = g_rowptr[n], e = g_rowptr[n + 1];
    for (int i = b; i < e; i++) {
        int s = g_csr[i];
        acc += g_dinv[s] * g_t3[s];
    }
    out[n] = dn * acc + b3[0];
}

// ---------------- launch ----------------------------------------------------
extern "C" void kernel_launch(void* const* d_in, const int* in_sizes, int n_in,
                              void* d_out, int out_size) {
    const float* x   = (const float*)d_in[0];
    const int*   ei  = (const int*)d_in[1];
    const float* W1  = (const float*)d_in[2];
    const float* b1  = (const float*)d_in[3];
    const float* W2  = (const float*)d_in[4];
    const float* b2  = (const float*)d_in[5];
    const float* W3  = (const float*)d_in[6];
    const float* b3  = (const float*)d_in[7];
    float* out = (float*)d_out;
    const int* src = ei;
    const int* dst = ei + NE;

    k_zero_cnt<<<(NN + 255) / 256, 256>>>();
    k_hist<<<(NE + 1023) / 1024, 256>>>(dst);
    k_scan_fused<<<1, 1024>>>();
    k_scatter<<<(NE + 1023) / 1024, 256>>>(src, dst);

    k_aggx<<<(NN * 32 + 255) / 256, 256>>>(x);
    k_gemm1<<<NN / 20, 256>>>(W1, b1);
    k_gemm2<<<NN / 32, 256>>>(W2);
    k_agg2dot<<<(NN * 32 + 255) / 256, 256>>>(b2, W3);
    k_agg3<<<(NN + 255) / 256, 256>>>(b3, out);
}

// round 7
// speedup vs baseline: 1.2589x; 1.2369x over previous
#include <cuda_runtime.h>
#include <cuda_bf16.h>

#define NN 20000
#define NP2 20096            // 157 * 128, row pad for gemm2
#define NE 320000
#define F0 10
#define F1 256
#define F2 128

// ---------------- scratch (device globals; zero-initialized) ----------------
__device__ int   g_cnt[NN];
__device__ int   g_rowptr[NN + 1];
__device__ int   g_rank[NE];           // per-edge rank within its dst bucket
__device__ int   g_csr[NE];            // src index per CSR slot (grouped by dst)
__device__ float g_dinv[NN];
__device__ float g_aggx[NN * F0];      // A_norm @ x
__device__ __nv_bfloat16 g_h1hi[NP2 * F1];   // relu(aggx@W1+b1) split-bf16 hi
__device__ __nv_bfloat16 g_h1lo[NP2 * F1];   // lo
__device__ __nv_bfloat16 g_w2thi[F2 * F1];   // W2^T [n][k] split-bf16 hi
__device__ __nv_bfloat16 g_w2tlo[F2 * F1];   // lo
__device__ float g_t2[NP2 * F2];       // h1 @ W2
__device__ float g_t3[NN];             // relu(A@t2+b2) @ W3

// -------- prep: zero cnt + convert/transpose W2 to split-bf16 ---------------
__global__ void k_prep(const float* __restrict__ W2) {
    int i = blockIdx.x * blockDim.x + threadIdx.x;   // 0..32767
    if (i < NN) g_cnt[i] = 0;
    if (i < F1 * F2) {
        int k = i / F2, n = i % F2;
        float v = W2[i];
        __nv_bfloat16 h = __float2bfloat16(v);
        __nv_bfloat16 l = __float2bfloat16(v - __bfloat162float(h));
        g_w2thi[n * F1 + k] = h;
        g_w2tlo[n * F1 + k] = l;
    }
}

// ---------------- CSR build ------------------------------------------------
__global__ void k_hist(const int* __restrict__ dst) {
    int e = blockIdx.x * blockDim.x + threadIdx.x;
    if (e < NE) g_rank[e] = atomicAdd(&g_cnt[dst[e]], 1);
}

// Single-block scan, one sync round; fuses g_dinv.
__global__ void k_scan_fused() {
    __shared__ int wsum[32];
    const int PER = 20;                       // 1024*20 = 20480 >= NN
    int tid  = threadIdx.x;
    int lane = tid & 31, w = tid >> 5;
    int base = tid * PER;

    int pref[PER];
    int s = 0;
    #pragma unroll
    for (int j = 0; j < PER; j++) {
        int idx = base + j;
        int c = (idx < NN) ? g_cnt[idx] : 0;
        pref[j] = s;
        s += c;
        if (idx < NN) g_dinv[idx] = rsqrtf((float)(c + 1));
    }

    int incl = s;
    #pragma unroll
    for (int o = 1; o < 32; o <<= 1) {
        int t = __shfl_up_sync(0xffffffffu, incl, o);
        if (lane >= o) incl += t;
    }
    if (lane == 31) wsum[w] = incl;
    __syncthreads();
    if (w == 0) {
        int t = wsum[lane];
        int ss = t;
        #pragma unroll
        for (int o = 1; o < 32; o <<= 1) {
            int u = __shfl_up_sync(0xffffffffu, ss, o);
            if (lane >= o) ss += u;
        }
        wsum[lane] = ss - t;
    }
    __syncthreads();

    int thread_excl = wsum[w] + incl - s;
    #pragma unroll
    for (int j = 0; j < PER; j++) {
        int idx = base + j;
        if (idx < NN) g_rowptr[idx] = thread_excl + pref[j];
    }
    if (tid == 1023) g_rowptr[NN] = thread_excl + s;  // == NE
}

// Atomic-free scatter: pos = rowptr[dst] + rank (rank captured during hist).
__global__ void k_scatter(const int* __restrict__ src, const int* __restrict__ dst) {
    int e = blockIdx.x * blockDim.x + threadIdx.x;
    if (e < NE) {
        int pos = g_rowptr[dst[e]] + g_rank[e];
        g_csr[pos] = src[e];
    }
}

// ---------------- layer 1: aggregate x (F=10), then GEMM -------------------
__global__ void k_aggx(const float* __restrict__ x) {
    int w = (blockIdx.x * blockDim.x + threadIdx.x) >> 5;
    int lane = threadIdx.x & 31;
    if (w >= NN) return;
    float dn = g_dinv[w];
    float acc = 0.f;
    if (lane < F0) acc = dn * x[w * F0 + lane];
    int b = g_rowptr[w], e = g_rowptr[w + 1];
    for (int i = b; i < e; i++) {
        int s = g_csr[i];
        float c = g_dinv[s];
        if (lane < F0) acc += c * x[s * F0 + lane];
    }
    if (lane < F0) g_aggx[w * F0 + lane] = dn * acc;
}

// [NN,10]@[10,256]+b1, relu; emit split-bf16 h1.  20 rows/block, 256 thr.
__global__ void k_gemm1(const float* __restrict__ W1, const float* __restrict__ b1) {
    __shared__ float Ws[F0 * F1];
    __shared__ float bs[F1];
    __shared__ float ax[20 * F0];
    int t = threadIdx.x;
    for (int i = t; i < F0 * F1; i += 256) Ws[i] = W1[i];
    bs[t] = b1[t];
    int r0 = blockIdx.x * 20;
    for (int i = t; i < 20 * F0; i += 256) ax[i] = g_aggx[r0 * F0 + i];
    __syncthreads();
    #pragma unroll 4
    for (int r = 0; r < 20; r++) {
        float acc = bs[t];
        #pragma unroll
        for (int k = 0; k < F0; k++) acc += ax[r * F0 + k] * Ws[k * F1 + t];
        float v = fmaxf(acc, 0.f);
        __nv_bfloat16 h = __float2bfloat16(v);
        __nv_bfloat16 l = __float2bfloat16(v - __bfloat162float(h));
        g_h1hi[(r0 + r) * F1 + t] = h;
        g_h1lo[(r0 + r) * F1 + t] = l;
    }
}

// ---------------- layer 2 GEMM (tensor cores, split-bf16) -------------------
// D[NP2,128] = h1[NP2,256] @ W2[256,128], 3-pass split bf16:
//   acc += a_hi*b_hi + a_lo*b_hi + a_hi*b_lo     (lo*lo dropped, ~2^-16)
// CTA: 128 rows, 8 warps x m16, full N=128 (16 n8-tiles), K chunked by 64.
__device__ __forceinline__ void mma_bf16(float* d, const unsigned* a,
                                         unsigned b0, unsigned b1) {
    asm volatile(
        "mma.sync.aligned.m16n8k16.row.col.f32.bf16.bf16.f32 "
        "{%0,%1,%2,%3}, {%4,%5,%6,%7}, {%8,%9}, {%0,%1,%2,%3};\n"
        : "+f"(d[0]), "+f"(d[1]), "+f"(d[2]), "+f"(d[3])
        : "r"(a[0]), "r"(a[1]), "r"(a[2]), "r"(a[3]), "r"(b0), "r"(b1));
}

#define KP 72   // smem B row stride (elems): conflict-free, 16B-aligned

__global__ void __launch_bounds__(256, 2) k_gemm2() {
    __shared__ __nv_bfloat16 bhi[F2 * KP];   // [n][k-chunk]
    __shared__ __nv_bfloat16 blo[F2 * KP];
    int t = threadIdx.x;
    int w = t >> 5, lane = t & 31;
    int r0 = blockIdx.x * 128;
    int mrow = r0 + w * 16 + (lane >> 2);    // A/D fragment top row
    int kq = (lane & 3) * 2;                 // k offset within 8

    float acc[16][4];
    #pragma unroll
    for (int i = 0; i < 16; i++)
        #pragma unroll
        for (int j = 0; j < 4; j++) acc[i][j] = 0.f;

    for (int kc = 0; kc < F1; kc += 64) {
        // stage B chunk: copy g_w2t{hi,lo}[n][kc..kc+63] -> smem [n][0..63]
        #pragma unroll
        for (int i = 0; i < 4; i++) {
            int idx = t + i * 256;           // 0..1023
            int n = idx >> 3, seg = idx & 7; // 8 x uint4 per row
            *(uint4*)&bhi[n * KP + seg * 8] =
                *(const uint4*)&g_w2thi[n * F1 + kc + seg * 8];
            *(uint4*)&blo[n * KP + seg * 8] =
                *(const uint4*)&g_w2tlo[n * F1 + kc + seg * 8];
        }
        __syncthreads();

        #pragma unroll
        for (int ks = 0; ks < 4; ks++) {
            int kg = kc + ks * 16 + kq;      // global k for A
            unsigned ahi[4], alo[4];
            ahi[0] = *(const unsigned*)&g_h1hi[ mrow      * F1 + kg];
            ahi[1] = *(const unsigned*)&g_h1hi[(mrow + 8) * F1 + kg];
            ahi[2] = *(const unsigned*)&g_h1hi[ mrow      * F1 + kg + 8];
            ahi[3] = *(const unsigned*)&g_h1hi[(mrow + 8) * F1 + kg + 8];
            alo[0] = *(const unsigned*)&g_h1lo[ mrow      * F1 + kg];
            alo[1] = *(const unsigned*)&g_h1lo[(mrow + 8) * F1 + kg];
            alo[2] = *(const unsigned*)&g_h1lo[ mrow      * F1 + kg + 8];
            alo[3] = *(const unsigned*)&g_h1lo[(mrow + 8) * F1 + kg + 8];
            int kl = ks * 16 + kq;           // chunk-local k for B
            #pragma unroll
            for (int nt = 0; nt < 16; nt++) {
                int nrow = nt * 8 + (lane >> 2);
                unsigned bh0 = *(const unsigned*)&bhi[nrow * KP + kl];
                unsigned bh1 = *(const unsigned*)&bhi[nrow * KP + kl + 8];
                unsigned bl0 = *(const unsigned*)&blo[nrow * KP + kl];
                unsigned bl1 = *(const unsigned*)&blo[nrow * KP + kl + 8];
                mma_bf16(acc[nt], ahi, bh0, bh1);
                mma_bf16(acc[nt], alo, bh0, bh1);
                mma_bf16(acc[nt], ahi, bl0, bl1);
            }
        }
        __syncthreads();
    }

    #pragma unroll
    for (int nt = 0; nt < 16; nt++) {
        int col = nt * 8 + (lane & 3) * 2;
        *(float2*)&g_t2[ mrow      * F2 + col] = make_float2(acc[nt][0], acc[nt][1]);
        *(float2*)&g_t2[(mrow + 8) * F2 + col] = make_float2(acc[nt][2], acc[nt][3]);
    }
}

// ------- layer 2 aggregation + bias + relu + layer-3 dot (fused) -----------
__global__ void k_agg2dot(const float* __restrict__ b2, const float* __restrict__ W3) {
    int w = (blockIdx.x * blockDim.x + threadIdx.x) >> 5;
    int lane = threadIdx.x & 31;
    if (w >= NN) return;
    float dn = g_dinv[w];
    int c4 = lane * 4;
    float4 sv = *(const float4*)&g_t2[w * F2 + c4];
    float4 acc = make_float4(dn * sv.x, dn * sv.y, dn * sv.z, dn * sv.w);
    int b = g_rowptr[w], e = g_rowptr[w + 1];
    for (int i = b; i < e; i++) {
        int s = g_csr[i];
        float c = g_dinv[s];
        float4 v = *(const float4*)&g_t2[s * F2 + c4];
        acc.x += c * v.x; acc.y += c * v.y; acc.z += c * v.z; acc.w += c * v.w;
    }
    float4 bb = *(const float4*)&b2[c4];
    float4 h;
    h.x = fmaxf(dn * acc.x + bb.x, 0.f);
    h.y = fmaxf(dn * acc.y + bb.y, 0.f);
    h.z = fmaxf(dn * acc.z + bb.z, 0.f);
    h.w = fmaxf(dn * acc.w + bb.w, 0.f);
    float4 v3 = *(const float4*)&W3[c4];
    float s = h.x * v3.x + h.y * v3.y + h.z * v3.z + h.w * v3.w;
    #pragma unroll
    for (int o = 16; o > 0; o >>= 1) s += __shfl_down_sync(0xffffffffu, s, o);
    if (lane == 0) g_t3[w] = s;
}

// ---------------- final aggregation over t3 --------------------------------
__global__ void k_agg3(const float* __restrict__ b3, float* __restrict__ out) {
    int n = blockIdx.x * blockDim.x + threadIdx.x;
    if (n >= NN) return;
    float dn = g_dinv[n];
    float acc = dn * g_t3[n];
    int b = g_rowptr[n], e = g_rowptr[n + 1];
    for (int i = b; i < e; i++) {
        int s = g_csr[i];
        acc += g_dinv[s] * g_t3[s];
    }
    out[n] = dn * acc + b3[0];
}

// ---------------- launch ----------------------------------------------------
extern "C" void kernel_launch(void* const* d_in, const int* in_sizes, int n_in,
                              void* d_out, int out_size) {
    const float* x   = (const float*)d_in[0];
    const int*   ei  = (const int*)d_in[1];
    const float* W1  = (const float*)d_in[2];
    const float* b1  = (const float*)d_in[3];
    const float* W2  = (const float*)d_in[4];
    const float* b2  = (const float*)d_in[5];
    const float* W3  = (const float*)d_in[6];
    const float* b3  = (const float*)d_in[7];
    float* out = (float*)d_out;
    const int* src = ei;
    const int* dst = ei + NE;

    k_prep<<<128, 256>>>(W2);                       // zero cnt + W2 split-bf16^T
    k_hist<<<(NE + 255) / 256, 256>>>(dst);
    k_scan_fused<<<1, 1024>>>();
    k_scatter<<<(NE + 255) / 256, 256>>>(src, dst);

    k_aggx<<<(NN * 32 + 255) / 256, 256>>>(x);
    k_gemm1<<<NN / 20, 256>>>(W1, b1);
    k_gemm2<<<NP2 / 128, 256>>>();
    k_agg2dot<<<(NN * 32 + 255) / 256, 256>>>(b2, W3);
    k_agg3<<<(NN + 255) / 256, 256>>>(b3, out);
}